// round 12
// baseline (speedup 1.0000x reference)
#include <cuda_runtime.h>
#include <stdint.h>

#define GRID_N 256

// dx = fp32(20/255); R = fp32(1/dx). XLA rewrites A/dx -> A*(1/dx), constant-folded.
#define DXF (20.0f / 255.0f)
#define RF  (1.0f / DXF)

__device__ __forceinline__ uint64_t make_evict_last_policy()
{
    uint64_t p;
    asm("createpolicy.fractional.L2::evict_last.b64 %0, 1.0;" : "=l"(p));
    return p;
}

__device__ __forceinline__ void red_add_evict_last(float* addr, float v, uint64_t policy)
{
    asm volatile("red.global.add.L2::cache_hint.f32 [%0], %1, %2;"
                 :: "l"(addr), "f"(v), "l"(policy) : "memory");
}

__device__ __forceinline__ void st_zero4_evict_last(float4* addr, uint64_t policy)
{
    asm volatile("st.global.L2::cache_hint.v4.f32 [%0], {%1, %1, %1, %1}, %2;"
                 :: "l"(addr), "f"(0.0f), "l"(policy) : "memory");
}

// Zero the grid with evict_last priority: parks all 67MB in L2 at top retention
// priority before the particle stream competes for capacity.
__global__ void __launch_bounds__(256) zero_grid_kernel(float* __restrict__ grid, int n_cells)
{
    uint64_t policy = make_evict_last_policy();
    int t = blockIdx.x * blockDim.x + threadIdx.x;
    int stride = gridDim.x * blockDim.x;
    int n4 = n_cells / 4;
    float4* g4 = (float4*)grid;
    for (int i = t; i < n4; i += stride)
        st_zero4_evict_last(&g4[i], policy);
}

// flat cell index, or -1 if out of grid
__device__ __forceinline__ int cell_index(float px, float py, float pz)
{
    // fi = (p + 10) * R ; then fi + 0.5, trunc toward zero.
    // __fmul_rn/__fadd_rn forbid FFMA contraction (XLA emits separate mul/add).
    float fx = __fadd_rn(__fmul_rn(__fadd_rn(px, 10.0f), RF), 0.5f);
    float fy = __fadd_rn(__fmul_rn(__fadd_rn(py, 10.0f), RF), 0.5f);
    float fz = __fadd_rn(__fmul_rn(__fadd_rn(pz, 10.0f), RF), 0.5f);

    int ix = (int)fx;   // cvt.rzi: trunc toward zero == astype(int32)
    int iy = (int)fy;
    int iz = (int)fz;

    bool in_grid = (ix >= 0) & (ix < GRID_N) &
                   (iy >= 0) & (iy < GRID_N) &
                   (iz >= 0) & (iz < GRID_N);
    return in_grid ? (ix * GRID_N + iy) * GRID_N + iz : -1;
}

// 8 particles per thread: batch all 8 LDG.128 first (MLP=8), then 8 REDGs
// back-to-back (long uninterrupted LSU burst).
__global__ void __launch_bounds__(256) scatter_kernel_v8(
    const float* __restrict__ positions,  // [N,3]
    const float* __restrict__ weights,    // [N]
    float* __restrict__ grid,
    int n_particles)
{
    int t = blockIdx.x * blockDim.x + threadIdx.x;
    int base = 8 * t;
    uint64_t policy = make_evict_last_policy();

    if (base + 7 < n_particles) {
        const float4* p4 = (const float4*)positions;
        const float4* w4 = (const float4*)weights;
        // 6 position vectors (24 floats = 8 particles) + 2 weight vectors
        float4 a = __ldcs(&p4[6 * t + 0]);
        float4 b = __ldcs(&p4[6 * t + 1]);
        float4 c = __ldcs(&p4[6 * t + 2]);
        float4 d = __ldcs(&p4[6 * t + 3]);
        float4 e = __ldcs(&p4[6 * t + 4]);
        float4 f = __ldcs(&p4[6 * t + 5]);
        float4 w0 = __ldcs(&w4[2 * t + 0]);
        float4 w1 = __ldcs(&w4[2 * t + 1]);

        int idx[8];
        idx[0] = cell_index(a.x, a.y, a.z);
        idx[1] = cell_index(a.w, b.x, b.y);
        idx[2] = cell_index(b.z, b.w, c.x);
        idx[3] = cell_index(c.y, c.z, c.w);
        idx[4] = cell_index(d.x, d.y, d.z);
        idx[5] = cell_index(d.w, e.x, e.y);
        idx[6] = cell_index(e.z, e.w, f.x);
        idx[7] = cell_index(f.y, f.z, f.w);

        float wt[8] = {w0.x, w0.y, w0.z, w0.w, w1.x, w1.y, w1.z, w1.w};

        #pragma unroll
        for (int j = 0; j < 8; j++)
            if (idx[j] >= 0) red_add_evict_last(&grid[idx[j]], wt[j], policy);
    } else if (base < n_particles) {
        // Tail: scalar per-particle.
        for (int i = base; i < n_particles; i++) {
            float px = __ldcs(&positions[3 * i + 0]);
            float py = __ldcs(&positions[3 * i + 1]);
            float pz = __ldcs(&positions[3 * i + 2]);
            float w  = __ldcs(&weights[i]);
            int idx = cell_index(px, py, pz);
            if (idx >= 0) red_add_evict_last(&grid[idx], w, policy);
        }
    }
}

extern "C" void kernel_launch(void* const* d_in, const int* in_sizes, int n_in,
                              void* d_out, int out_size)
{
    const float* positions = (const float*)d_in[0];
    const float* weights   = (const float*)d_in[1];
    float* grid            = (float*)d_out;

    int n_particles = in_sizes[1];  // weights has N elements; positions has 3N

    {
        int threads = 256;
        int blocks = 148 * 8;   // one wave, grid-stride
        zero_grid_kernel<<<blocks, threads>>>(grid, out_size);
    }

    int threads = 256;
    int n_threads_total = (n_particles + 7) / 8;
    int blocks = (n_threads_total + threads - 1) / threads;
    scatter_kernel_v8<<<blocks, threads>>>(positions, weights, grid, n_particles);
}